// round 1
// baseline (speedup 1.0000x reference)
#include <cuda_runtime.h>

#define BATCH 8
#define HH 512
#define WW 512
#define NPIX (HH * WW)
#define NTOT (BATCH * NPIX)

// ---------------------------------------------------------------------------
// Compile-time parsing of the binary endpoint kernels (bit i*k+j = ker[i][j]).
// ---------------------------------------------------------------------------
__host__ __device__ constexpr unsigned long long kbits(const char* s) {
    unsigned long long m = 0;
    for (int i = 0; s[i]; ++i)
        if (s[i] == '1') m |= (1ull << i);
    return m;
}

// ---------------------------------------------------------------------------
// Scratch (allocation-free: __device__ globals)
// ---------------------------------------------------------------------------
__device__ float g_bufP1[NTOT];
__device__ float g_bufG1[NTOT];
__device__ float g_bufP2[NTOT];
__device__ float g_bufG2[NTOT];
__device__ float g_cmax[4];   // erosion conv maxima: P1,G1,P2,G2
__device__ float g_lm[6];     // level tensor maxima: P0,G0,P1,G1,P2,G2
__device__ double g_loss;

__device__ __forceinline__ const float* pick(int sel, const float* pred, const float* gt) {
    switch (sel) {
        case 0: return pred;
        case 1: return gt;
        case 2: return g_bufP1;
        case 3: return g_bufG1;
        case 4: return g_bufP2;
        default: return g_bufG2;
    }
}
__device__ __forceinline__ float* pick_buf(int sel) {
    switch (sel) {
        case 0: return g_bufP1;
        case 1: return g_bufG1;
        case 2: return g_bufP2;
        default: return g_bufG2;
    }
}

__device__ __forceinline__ float sigm(float x) {
    return __fdividef(1.0f, 1.0f + __expf(-x));
}

__device__ __forceinline__ float endpoint_sig(float nc) {
    float z = -10.0f * (nc - 1.0f);
    z = fminf(10.0f, fmaxf(-10.0f, z));
    return sigm(z);
}

// ---------------------------------------------------------------------------
// Block reductions (256 threads)
// ---------------------------------------------------------------------------
__device__ __forceinline__ float blockReduceSum(float v) {
    __shared__ float sh[8];
#pragma unroll
    for (int o = 16; o > 0; o >>= 1) v += __shfl_down_sync(0xffffffffu, v, o);
    int lane = threadIdx.x & 31, wid = threadIdx.x >> 5;
    if (lane == 0) sh[wid] = v;
    __syncthreads();
    v = (threadIdx.x < 8) ? sh[threadIdx.x] : 0.0f;
    if (wid == 0) {
#pragma unroll
        for (int o = 4; o > 0; o >>= 1) v += __shfl_down_sync(0xffffffffu, v, o);
    }
    return v;
}

__device__ __forceinline__ float blockReduceMax(float v) {
    __shared__ float sh[8];
#pragma unroll
    for (int o = 16; o > 0; o >>= 1) v = fmaxf(v, __shfl_down_sync(0xffffffffu, v, o));
    int lane = threadIdx.x & 31, wid = threadIdx.x >> 5;
    if (lane == 0) sh[wid] = v;
    __syncthreads();
    v = (threadIdx.x < 8) ? sh[threadIdx.x] : 0.0f;
    if (wid == 0) {
#pragma unroll
        for (int o = 4; o > 0; o >>= 1) v = fmaxf(v, __shfl_down_sync(0xffffffffu, v, o));
    }
    return v;
}

// ---------------------------------------------------------------------------
// cp-map inner value at padded coordinate q (window = 6x6 of padded values,
// base points at padded coord (q-3, q-3), row stride INSTRIDE).
// Frame row for kernel-size k element i:  i - k/2 + 3.
// ---------------------------------------------------------------------------
#define INSTRIDE 40

__device__ __forceinline__ float cp_value(const float* __restrict__ base) {
    float w[36];
#pragma unroll
    for (int r = 0; r < 6; ++r)
#pragma unroll
        for (int c = 0; c < 6; ++c) w[r * 6 + c] = base[r * INSTRIDE + c];

    float ssum = 0.0f;
    {
        constexpr unsigned long long KB[8] = {
            kbits("111001111"), kbits("111101101"), kbits("111100111"), kbits("101101111"),
            kbits("011101111"), kbits("111101011"), kbits("111101110"), kbits("110101111")};
#pragma unroll
        for (int kk = 0; kk < 8; ++kk) {
            float nc = 0.0f;
#pragma unroll
            for (int i = 0; i < 3; ++i)
#pragma unroll
                for (int j = 0; j < 3; ++j)
                    if ((KB[kk] >> (i * 3 + j)) & 1ull) nc += w[(i + 2) * 6 + (j + 2)];
            ssum += endpoint_sig(nc);
        }
    }
    {
        constexpr unsigned long long KB[8] = {
            kbits("0011000110011111"), kbits("1100100010011111"),
            kbits("1111100100010011"), kbits("1111100110001100"),
            kbits("1001100110011111"), kbits("1111000100011111"),
            kbits("1111100110011001"), kbits("1111100010001111")};
#pragma unroll
        for (int kk = 0; kk < 8; ++kk) {
            float nc = 0.0f;
#pragma unroll
            for (int i = 0; i < 4; ++i)
#pragma unroll
                for (int j = 0; j < 4; ++j)
                    if ((KB[kk] >> (i * 4 + j)) & 1ull) nc += w[(i + 1) * 6 + (j + 1)];
            ssum += endpoint_sig(nc);
        }
    }
    {
        constexpr unsigned long long KB[8] = {
            kbits("0001100001000011000111111"), kbits("1100010000100001000111111"),
            kbits("1111110001100001000011000"), kbits("1111110001000010000100011"),
            kbits("1111110000100001000011111"), kbits("1111100001000010000111111"),
            kbits("1111110001100011000110001"), kbits("1000110001100011000111111")};
#pragma unroll
        for (int kk = 0; kk < 8; ++kk) {
            float nc = 0.0f;
#pragma unroll
            for (int i = 0; i < 5; ++i)
#pragma unroll
                for (int j = 0; j < 5; ++j)
                    if ((KB[kk] >> (i * 5 + j)) & 1ull) nc += w[(i + 1) * 6 + (j + 1)];
            ssum += endpoint_sig(nc);
        }
    }
    {
        // GROUPS[3] = first 7 of the 8 k=6 kernels
        constexpr unsigned long long KB[7] = {
            kbits("000011000001000001000001100001111111"),
            kbits("110000100000100000100000100001111111"),
            kbits("111111100001100000100000100000110000"),
            kbits("111111100001000001000001000001000011"),
            kbits("111111100000100000100000100000111111"),
            kbits("111111000001000001000001000001111111"),
            kbits("111111100001100001100001100001100001")};
#pragma unroll
        for (int kk = 0; kk < 7; ++kk) {
            float nc = 0.0f;
#pragma unroll
            for (int i = 0; i < 6; ++i)
#pragma unroll
                for (int j = 0; j < 6; ++j)
                    if ((KB[kk] >> (i * 6 + j)) & 1ull) nc += w[i * 6 + j];
            ssum += endpoint_sig(nc);
        }
    }
    float epss = ssum * w[3 * 6 + 3];  // * padded[q] (interior => the data value)
    return sigm(10.0f * (epss - 0.5f));
}

// ---------------------------------------------------------------------------
// Fused get_cp + dilate + squared-diff kernel for one (pe, ge) pair.
// Tile: 32x32 outputs; cp region 34x34; padded-input region 39x39.
// comp!=0 => value = levelMax - stored (ring padding stays 1.0).
// ---------------------------------------------------------------------------
__global__ __launch_bounds__(256) void cp_pair_kernel(
    const float* __restrict__ pred, const float* __restrict__ gt,
    int selP, int selG, int lmP, int lmG, int comp) {
    __shared__ float smP[39 * INSTRIDE];
    __shared__ float smG[39 * INSTRIDE];
    __shared__ float cpP[34 * 36];
    __shared__ float cpG[34 * 36];

    const int b = blockIdx.z;
    const int ty0 = blockIdx.y * 32, tx0 = blockIdx.x * 32;
    const float* srcP = pick(selP, pred, gt) + (size_t)b * NPIX;
    const float* srcG = pick(selG, pred, gt) + (size_t)b * NPIX;

    float offP = 0.0f, offG = 0.0f, sgn = 1.0f;
    if (comp) { offP = g_lm[lmP]; offG = g_lm[lmG]; sgn = -1.0f; }

    // Load padded-coordinate tiles: 0 outside [0,513], 1 on the ring, data inside.
    for (int i = threadIdx.x; i < 39 * 39; i += 256) {
        int r = i / 39, c = i % 39;
        int qy = ty0 - 3 + r, qx = tx0 - 3 + c;
        float vP, vG;
        if (qy < 0 || qy > 513 || qx < 0 || qx > 513) {
            vP = 0.0f; vG = 0.0f;
        } else if (qy == 0 || qy == 513 || qx == 0 || qx == 513) {
            vP = 1.0f; vG = 1.0f;
        } else {
            int idx = (qy - 1) * WW + (qx - 1);
            vP = fmaf(sgn, srcP[idx], offP);
            vG = fmaf(sgn, srcG[idx], offG);
        }
        smP[r * INSTRIDE + c] = vP;
        smG[r * INSTRIDE + c] = vG;
    }
    __syncthreads();

    // cp maps (zero outside the 512x512 domain for the dilate zero-pad)
    for (int i = threadIdx.x; i < 34 * 34; i += 256) {
        int r = i / 34, c = i % 34;
        int y = ty0 - 1 + r, x = tx0 - 1 + c;
        float cP = 0.0f, cG = 0.0f;
        if (y >= 0 && y < HH && x >= 0 && x < WW) {
            cP = cp_value(&smP[r * INSTRIDE + c]);
            cG = cp_value(&smG[r * INSTRIDE + c]);
        }
        cpP[r * 36 + c] = cP;
        cpG[r * 36 + c] = cG;
    }
    __syncthreads();

    // dilate (3x3 ones, clip to [0,1]) + squared difference
    float acc = 0.0f;
    for (int i = threadIdx.x; i < 32 * 32; i += 256) {
        int r = i / 32, c = i % 32;
        float sP = 0.0f, sG = 0.0f;
#pragma unroll
        for (int dr = 0; dr < 3; ++dr)
#pragma unroll
            for (int dc = 0; dc < 3; ++dc) {
                sP += cpP[(r + dr) * 36 + (c + dc)];
                sG += cpG[(r + dr) * 36 + (c + dc)];
            }
        float d = fminf(sP, 1.0f) - fminf(sG, 1.0f);
        acc += d * d;
    }
    acc = blockReduceSum(acc);
    if (threadIdx.x == 0) atomicAdd(&g_loss, (double)acc);
}

// ---------------------------------------------------------------------------
// Erosion: cross conv + global max, then sig2 normalize.
// ---------------------------------------------------------------------------
__global__ __launch_bounds__(256) void erode_conv_kernel(
    const float* __restrict__ pred, const float* __restrict__ gt,
    int selSrc, int dstSel, int cmaxSlot) {
    int idx = blockIdx.x * blockDim.x + threadIdx.x;
    float s = 0.0f;
    if (idx < NTOT) {
        const float* src = pick(selSrc, pred, gt);
        int x = idx & (WW - 1), y = (idx >> 9) & (HH - 1);
        if (y > 0)      s += src[idx - WW];
        if (y < HH - 1) s += src[idx + WW];
        if (x > 0)      s += src[idx - 1];
        if (x < WW - 1) s += src[idx + 1];
        pick_buf(dstSel)[idx] = s;
    }
    float m = blockReduceMax(s);
    if (threadIdx.x == 0) atomicMax((int*)&g_cmax[cmaxSlot], __float_as_int(m));
}

__global__ __launch_bounds__(256) void erode_norm_kernel(int bufSel, int cmaxSlot, int lmSlot) {
    int idx = blockIdx.x * blockDim.x + threadIdx.x;
    float M = g_cmax[cmaxSlot];
    float inv = __fdividef(1.0f, M + 1e-8f);
    if (idx < NTOT) {
        float* buf = pick_buf(bufSel);
        buf[idx] = sigm(10.0f * (buf[idx] * inv - 0.7f));
    }
    if (idx == 0) g_lm[lmSlot] = sigm(10.0f * (M * inv - 0.7f));
}

__global__ __launch_bounds__(256) void max_kernel(const float* __restrict__ src, int lmSlot) {
    int idx = blockIdx.x * blockDim.x + threadIdx.x;
    float v = (idx < NTOT) ? src[idx] : 0.0f;
    float m = blockReduceMax(v);
    if (threadIdx.x == 0) atomicMax((int*)&g_lm[lmSlot], __float_as_int(m));
}

__global__ void init_kernel() {
    if (threadIdx.x == 0) {
        g_loss = 0.0;
#pragma unroll
        for (int i = 0; i < 4; ++i) g_cmax[i] = 0.0f;
#pragma unroll
        for (int i = 0; i < 6; ++i) g_lm[i] = 0.0f;
    }
}

__global__ void final_kernel(float* out) {
    out[0] = (float)(g_loss * (1.0 / (double)BATCH));
}

// ---------------------------------------------------------------------------
// Launch: pyramids -> 12 fused pair kernels -> scalar. Graph-capturable.
// ---------------------------------------------------------------------------
extern "C" void kernel_launch(void* const* d_in, const int* in_sizes, int n_in,
                              void* d_out, int out_size) {
    const float* pred = (const float*)d_in[0];
    const float* gt = (const float*)d_in[1];
    float* out = (float*)d_out;

    const int nb = NTOT / 256;

    init_kernel<<<1, 32>>>();
    max_kernel<<<nb, 256>>>(pred, 0);
    max_kernel<<<nb, 256>>>(gt, 1);

    // level 1
    erode_conv_kernel<<<nb, 256>>>(pred, gt, /*src*/0, /*dst*/0, /*cmax*/0);  // pred -> bufP1
    erode_norm_kernel<<<nb, 256>>>(0, 0, /*lm*/2);
    erode_conv_kernel<<<nb, 256>>>(pred, gt, 1, 1, 1);                        // gt -> bufG1
    erode_norm_kernel<<<nb, 256>>>(1, 1, 3);
    // level 2
    erode_conv_kernel<<<nb, 256>>>(pred, gt, 2, 2, 2);                        // bufP1 -> bufP2
    erode_norm_kernel<<<nb, 256>>>(2, 2, 4);
    erode_conv_kernel<<<nb, 256>>>(pred, gt, 3, 3, 3);                        // bufG1 -> bufG2
    erode_norm_kernel<<<nb, 256>>>(3, 3, 5);

    dim3 grid(WW / 32, HH / 32, BATCH);
    for (int lvl = 0; lvl < 3; ++lvl) {
        int selP = (lvl == 0) ? 0 : (lvl == 1 ? 2 : 4);
        int selG = (lvl == 0) ? 1 : (lvl == 1 ? 3 : 5);
        int lmP = 2 * lvl, lmG = 2 * lvl + 1;
        cp_pair_kernel<<<grid, 256>>>(pred, gt, selP, selG, lmP, lmG, 0);
        cp_pair_kernel<<<grid, 256>>>(pred, gt, selP, selG, lmP, lmG, 1);
    }

    final_kernel<<<1, 1>>>(out);
}